// round 14
// baseline (speedup 1.0000x reference)
#include <cuda_runtime.h>
#include <cuda_fp16.h>
#include <math.h>
#include <stdint.h>

#define BATCH 4096
#define DIM   512
#define NCLS  10

#define BM 128
#define NBLK (BATCH / BM)            // 32
#define NTRI (NBLK * (NBLK + 1) / 2) // 528 tiles (32 diag first, 496 off-diag)

#define NCHUNK 8                     // K chunks of 64 halves
#define KCHUNK 64
#define NSTAGE 3

#define RSTRIDE 144                          // bytes per smem row (64 fp16 + 16B pad)
#define TILE_BYTES (128 * RSTRIDE)           // 18432
#define ABUF(b) ((b) * 2 * TILE_BYTES)
#define BBUF(b) ((b) * 2 * TILE_BYTES + TILE_BYTES)
#define SMEM_DYN (NSTAGE * 2 * TILE_BYTES)   // 110592 bytes

// Scratch (device globals -- no allocation allowed; zero-initialized)
__device__ __half g_normh[BATCH * DIM];  // fp16 normalized features (4 MB)
__device__ int    g_cls[BATCH];
__device__ float  g_pos[BATCH];
__device__ float  g_all[BATCH];
__device__ int    g_ready[NBLK];         // block-normalized flags (self-resetting)
__device__ unsigned g_done;              // CTA completion counter (self-resetting)

// ---------------------------------------------------------------------------
__device__ __forceinline__ uint32_t smem_u32(const void* p) {
    uint32_t a;
    asm("{ .reg .u64 t; cvta.to.shared.u64 t, %1; cvt.u32.u64 %0, t; }"
        : "=r"(a) : "l"(p));
    return a;
}

#define LDSM_X4(d, addr) \
    asm volatile("ldmatrix.sync.aligned.m8n8.x4.shared.b16 {%0,%1,%2,%3}, [%4];" \
                 : "=r"((d)[0]), "=r"((d)[1]), "=r"((d)[2]), "=r"((d)[3]) \
                 : "r"(addr))

// fp16 accumulate m16n8k16 -- measured best legacy tensor rate on sm_103
__device__ __forceinline__ void mma_f16h(uint32_t* c, const uint32_t* a,
                                         uint32_t b0, uint32_t b1) {
    asm volatile(
        "mma.sync.aligned.m16n8k16.row.col.f16.f16.f16.f16 "
        "{%0,%1}, {%2,%3,%4,%5}, {%6,%7}, {%0,%1};"
        : "+r"(c[0]), "+r"(c[1])
        : "r"(a[0]), "r"(a[1]), "r"(a[2]), "r"(a[3]), "r"(b0), "r"(b1));
}

__device__ __forceinline__ float fast_exp2(float x) {
    float r;
    asm("ex2.approx.ftz.f32 %0, %1;" : "=f"(r) : "f"(x));
    return r;
}

__device__ __forceinline__ uint32_t pack_h2(float a, float b) {
    uint32_t r;
    asm("{ .reg .b16 l, h;\n\t"
        "cvt.rn.f16.f32 l, %1;\n\t"
        "cvt.rn.f16.f32 h, %2;\n\t"
        "mov.b32 %0, {l, h}; }" : "=r"(r) : "f"(a), "f"(b));
    return r;
}

// ---------------------------------------------------------------------------
// Fused kernel: diag CTAs (bid 0..31) normalize their block then compute their
// tile; off-diag CTAs spin on both block flags then compute; the 528th CTA to
// finish runs the loss reduction and resets the flags for the next replay.
// ---------------------------------------------------------------------------
__global__ void __launch_bounds__(512, 2)
contrastive_fused_kernel(float* __restrict__ out,
                         const float* __restrict__ feats,
                         const float* __restrict__ labels) {
    extern __shared__ char smem[];
    __shared__ int clsA_s[128];
    __shared__ int clsB_s[128];
    __shared__ unsigned s_last;
    const uint32_t sb = smem_u32(smem);

    const int tid = threadIdx.x;
    const int lane = tid & 31;
    const int wid = tid >> 5;
    const int wr = wid >> 2;        // 0..3 warp row (32 rows each)
    const int wc = wid & 3;         // 0..3 warp col (32 cols each)
    const int g = lane >> 2;        // 0..7
    const int tig = lane & 3;       // 0..3

    // tile mapping: bid < 32 -> diagonal (guaranteed wave-1 resident);
    // bid >= 32 -> off-diagonal pairs (by < bx)
    int by, bx;
    if (blockIdx.x < NBLK) {
        by = bx = blockIdx.x;
    } else {
        int t = blockIdx.x - NBLK;
        by = 0;
        while (t >= NBLK - 1 - by) { t -= NBLK - 1 - by; by++; }
        bx = by + 1 + t;
    }
    const bool isDiag = (bx == by);
    const int rowBase = by * BM;
    const int colBase = bx * BM;

    // ---- phase 0: normalize own block (diag) or wait for flags (off-diag) ----
    if (isDiag) {
        // 16 warps x 2 rows x 4 iterations = 128 rows
#pragma unroll 1
        for (int it = 0; it < 4; it++) {
            const int row0 = rowBase + it * 32 + wid * 2;
            const int row1 = row0 + 1;
            float4 v0[4], v1[4];
            float s0 = 0.0f, s1 = 0.0f;
#pragma unroll
            for (int k = 0; k < 4; k++) {
                v0[k] = ((const float4*)(feats + row0 * DIM))[k * 32 + lane];
                v1[k] = ((const float4*)(feats + row1 * DIM))[k * 32 + lane];
            }
#pragma unroll
            for (int k = 0; k < 4; k++) {
                s0 += v0[k].x * v0[k].x + v0[k].y * v0[k].y
                    + v0[k].z * v0[k].z + v0[k].w * v0[k].w;
                s1 += v1[k].x * v1[k].x + v1[k].y * v1[k].y
                    + v1[k].z * v1[k].z + v1[k].w * v1[k].w;
            }
#pragma unroll
            for (int o = 16; o > 0; o >>= 1) {
                s0 += __shfl_xor_sync(0xffffffffu, s0, o);
                s1 += __shfl_xor_sync(0xffffffffu, s1, o);
            }
            float i0 = 1.0f / sqrtf(s0);
            float i1 = 1.0f / sqrtf(s1);
#pragma unroll
            for (int k = 0; k < 4; k++) {
                uint2 u0, u1;
                u0.x = pack_h2(v0[k].x * i0, v0[k].y * i0);
                u0.y = pack_h2(v0[k].z * i0, v0[k].w * i0);
                u1.x = pack_h2(v1[k].x * i1, v1[k].y * i1);
                u1.y = pack_h2(v1[k].z * i1, v1[k].w * i1);
                ((uint2*)(g_normh + row0 * DIM))[k * 32 + lane] = u0;
                ((uint2*)(g_normh + row1 * DIM))[k * 32 + lane] = u1;
            }
            if (lane < NCLS) {
                if (labels[row0 * NCLS + lane] > 0.5f) g_cls[row0] = lane;
            } else if (lane >= 16 && lane < 16 + NCLS) {
                if (labels[row1 * NCLS + (lane - 16)] > 0.5f) g_cls[row1] = lane - 16;
            }
            if (lane == 0) { g_pos[row0] = 0.0f; g_all[row0] = 0.0f; }
            if (lane == 1) { g_pos[row1] = 0.0f; g_all[row1] = 0.0f; }
        }
        __threadfence();           // publish block data before the flag (32 CTAs only)
        __syncthreads();
        if (tid == 0) atomicExch(&g_ready[by], 1);
    } else {
        if (tid == 0) {
            while (*(volatile int*)&g_ready[by] == 0) { }
            while (*(volatile int*)&g_ready[bx] == 0) { }
        }
        __syncthreads();           // all threads gated behind the flags
    }

    // cls tiles (reads gated behind flags; first touch -> L2-correct)
    if (tid < 128) clsA_s[tid] = g_cls[rowBase + tid];
    else if (tid < 256) clsB_s[tid - 128] = g_cls[colBase + (tid - 128)];

    // per-lane ldmatrix offsets (bytes within tile)
    const int mA = lane >> 3;       // matrix index 0..3
    const int rA = lane & 7;
    const uint32_t aOff = (uint32_t)((wr * 32 + (mA & 1) * 8 + rA) * RSTRIDE
                                     + (mA >> 1) * 16);
    const uint32_t bOff = (uint32_t)((wc * 32 + (mA >> 1) * 8 + rA) * RSTRIDE
                                     + (mA & 1) * 16);

    // fp16 accumulators: [mi][ni][h] -> b32 holding cols (tig*2, tig*2+1)
    uint32_t hacc[2][4][2];
#pragma unroll
    for (int mi = 0; mi < 2; mi++)
#pragma unroll
        for (int ni = 0; ni < 4; ni++) {
            hacc[mi][ni][0] = 0u;
            hacc[mi][ni][1] = 0u;
        }

    auto load_chunk = [&](int c) {
        const int buf = c % NSTAGE;
        const int k0 = c * KCHUNK;
#pragma unroll
        for (int it = 0; it < 4; it++) {
            int flat = it * 512 + tid;      // 0..2047 16B segments
            int tile = flat >> 10;          // 0 = A, 1 = B
            if (tile == 1 && isDiag) continue;   // diag: B aliases A
            int r = (flat >> 3) & 127;
            int seg = flat & 7;
            const __half* src = g_normh
                + (size_t)((tile ? colBase : rowBase) + r) * DIM + k0 + seg * 8;
            uint32_t dst = sb + (tile ? BBUF(buf) : ABUF(buf))
                         + r * RSTRIDE + seg * 16;
            asm volatile("cp.async.cg.shared.global [%0], [%1], 16;"
                         :: "r"(dst), "l"(src) : "memory");
        }
        asm volatile("cp.async.commit_group;" ::: "memory");
    };

    auto compute_chunk = [&](int buf) {
        const uint32_t aBase = sb + ABUF(buf) + aOff;
        const uint32_t bBase = (isDiag ? sb + ABUF(buf) : sb + BBUF(buf)) + bOff;
#pragma unroll
        for (int ks = 0; ks < 4; ks++) {       // four k16 steps per 64-chunk
            uint32_t a[2][4], b[2][4];
#pragma unroll
            for (int mi = 0; mi < 2; mi++)
                LDSM_X4(a[mi], aBase + mi * (16 * RSTRIDE) + ks * 32);
#pragma unroll
            for (int p = 0; p < 2; p++)        // p covers cols wc*32 + p*16
                LDSM_X4(b[p], bBase + p * (16 * RSTRIDE) + ks * 32);
#pragma unroll
            for (int mi = 0; mi < 2; mi++)
#pragma unroll
                for (int ni = 0; ni < 4; ni++)
                    mma_f16h(hacc[mi][ni], a[mi],
                             b[ni >> 1][2 * (ni & 1)], b[ni >> 1][2 * (ni & 1) + 1]);
        }
    };

    // ---- 3-stage pipelined mainloop: one __syncthreads per chunk ----
    load_chunk(0);
    load_chunk(1);
    for (int c = 0; c < NCHUNK; c++) {
        if (c < NCHUNK - 1)
            asm volatile("cp.async.wait_group 1;" ::: "memory");
        else
            asm volatile("cp.async.wait_group 0;" ::: "memory");
        __syncthreads();
        if (c + 2 < NCHUNK) load_chunk(c + 2);
        compute_chunk(c % NSTAGE);
    }

    // ---- register-only epilogue (no clip: |sim|<=1 -> |sim/T|<=14.3 < 20) ----
    const float SCL = 1.44269504088896f / 0.07f;   // exp(x/T) = exp2(x*SCL)

    int rcls[2][2], ccls[4][2];
#pragma unroll
    for (int mi = 0; mi < 2; mi++)
#pragma unroll
        for (int h = 0; h < 2; h++)
            rcls[mi][h] = clsA_s[wr * 32 + mi * 16 + h * 8 + g];
#pragma unroll
    for (int ni = 0; ni < 4; ni++)
#pragma unroll
        for (int q = 0; q < 2; q++)
            ccls[ni][q] = clsB_s[wc * 32 + ni * 8 + tig * 2 + q];

    float rAll[2][2], rPos[2][2], cAll[4][2], cPos[4][2];
#pragma unroll
    for (int i = 0; i < 2; i++)
#pragma unroll
        for (int h = 0; h < 2; h++) { rAll[i][h] = 0.0f; rPos[i][h] = 0.0f; }
#pragma unroll
    for (int i = 0; i < 4; i++)
#pragma unroll
        for (int q = 0; q < 2; q++) { cAll[i][q] = 0.0f; cPos[i][q] = 0.0f; }

#pragma unroll
    for (int mi = 0; mi < 2; mi++)
#pragma unroll
        for (int ni = 0; ni < 4; ni++)
#pragma unroll
            for (int h = 0; h < 2; h++) {
                float2 vv = __half22float2(
                    *reinterpret_cast<__half2*>(&hacc[mi][ni][h]));
#pragma unroll
                for (int q = 0; q < 2; q++) {
                    float e = fast_exp2((q ? vv.y : vv.x) * SCL);
                    if (isDiag) {
                        int rl = wr * 32 + mi * 16 + h * 8 + g;
                        int cl = wc * 32 + ni * 8 + tig * 2 + q;
                        if (rl == cl) e = 0.0f;
                    }
                    rAll[mi][h] += e;
                    cAll[ni][q] += e;
                    if (rcls[mi][h] == ccls[ni][q]) {
                        rPos[mi][h] += e;
                        cPos[ni][q] += e;
                    }
                }
            }

    // row sums: reduce over tig (lane bits 0,1)
#pragma unroll
    for (int mi = 0; mi < 2; mi++)
#pragma unroll
        for (int h = 0; h < 2; h++) {
#pragma unroll
            for (int o = 1; o < 4; o <<= 1) {
                rAll[mi][h] += __shfl_xor_sync(0xffffffffu, rAll[mi][h], o);
                rPos[mi][h] += __shfl_xor_sync(0xffffffffu, rPos[mi][h], o);
            }
        }
    if (tig == 0) {
#pragma unroll
        for (int mi = 0; mi < 2; mi++)
#pragma unroll
            for (int h = 0; h < 2; h++) {
                int gr = rowBase + wr * 32 + mi * 16 + h * 8 + g;
                atomicAdd(&g_all[gr], rAll[mi][h]);
                atomicAdd(&g_pos[gr], rPos[mi][h]);
            }
    }

    // symmetric column sums (off-diagonal only): reduce over g (lane bits 2..4)
    if (!isDiag) {
#pragma unroll
        for (int ni = 0; ni < 4; ni++)
#pragma unroll
            for (int q = 0; q < 2; q++) {
#pragma unroll
                for (int o = 4; o < 32; o <<= 1) {
                    cAll[ni][q] += __shfl_xor_sync(0xffffffffu, cAll[ni][q], o);
                    cPos[ni][q] += __shfl_xor_sync(0xffffffffu, cPos[ni][q], o);
                }
            }
        if (g == 0) {
#pragma unroll
            for (int ni = 0; ni < 4; ni++)
#pragma unroll
                for (int q = 0; q < 2; q++) {
                    int gc = colBase + wc * 32 + ni * 8 + tig * 2 + q;
                    atomicAdd(&g_all[gc], cAll[ni][q]);
                    atomicAdd(&g_pos[gc], cPos[ni][q]);
                }
        }
    }

    // ---- fused finalize: release-ordered done counter, last CTA reduces ----
    // All epilogue writes are atomics (L2-resident), so atom.release orders
    // them without an L1 flush. Reader uses __ldcg (L2-direct) loads.
    if (tid == 0) {
        unsigned old;
        asm volatile("atom.release.gpu.global.add.u32 %0, [%1], 1;"
                     : "=r"(old) : "l"(&g_done) : "memory");
        s_last = old;
    }
    __syncthreads();
    if (s_last == NTRI - 1) {
        __shared__ int cnt[NCLS];
        __shared__ float s_tot[16];
        __shared__ float s_cnt[16];
        if (tid < NCLS) cnt[tid] = 0;
        __syncthreads();
        for (int r = tid; r < BATCH; r += 512)
            atomicAdd(&cnt[__ldcg(&g_cls[r])], 1);
        __syncthreads();

        float total = 0.0f, nval = 0.0f;
        for (int r = tid; r < BATCH; r += 512) {
            int c = __ldcg(&g_cls[r]);
            if (cnt[c] >= 2) {
                float pos = __ldcg(&g_pos[r]);
                float all = __ldcg(&g_all[r]);
                total += -logf(pos / (all + 1e-8f) + 1e-8f);
                nval += 1.0f;
            }
        }
#pragma unroll
        for (int o = 16; o > 0; o >>= 1) {
            total += __shfl_xor_sync(0xffffffffu, total, o);
            nval  += __shfl_xor_sync(0xffffffffu, nval, o);
        }
        if (lane == 0) { s_tot[wid] = total; s_cnt[wid] = nval; }
        __syncthreads();
        if (tid == 0) {
            float tt = 0.0f, nn = 0.0f;
#pragma unroll
            for (int w = 0; w < 16; w++) { tt += s_tot[w]; nn += s_cnt[w]; }
            out[0] = (nn > 0.0f) ? tt / nn : 0.0f;
        }
        // reset state for the next graph replay
        if (tid < NBLK) g_ready[tid] = 0;
        if (tid == 0) g_done = 0;
    }
}

// ---------------------------------------------------------------------------
extern "C" void kernel_launch(void* const* d_in, const int* in_sizes, int n_in,
                              void* d_out, int out_size) {
    const float* features = (const float*)d_in[0];  // [4096, 512] f32
    const float* labels   = (const float*)d_in[1];  // [4096, 10]  f32
    float* out = (float*)d_out;

    cudaFuncSetAttribute(contrastive_fused_kernel,
                         cudaFuncAttributeMaxDynamicSharedMemorySize, SMEM_DYN);

    contrastive_fused_kernel<<<NTRI, 512, SMEM_DYN>>>(out, features, labels);
}

// round 15
// speedup vs baseline: 1.0985x; 1.0985x over previous
#include <cuda_runtime.h>
#include <cuda_fp16.h>
#include <math.h>
#include <stdint.h>

#define BATCH 4096
#define DIM   512
#define NCLS  10

#define BM 128
#define NBLK (BATCH / BM)            // 32
#define NTRI (NBLK * (NBLK + 1) / 2) // 528 upper-triangular tiles

#define NCHUNK 8                     // K chunks of 64 halves
#define KCHUNK 64
#define NSTAGE 3

#define RSTRIDE 144                          // bytes per smem row (64 fp16 + 16B pad)
#define TILE_BYTES (128 * RSTRIDE)           // 18432
#define ABUF(b) ((b) * 2 * TILE_BYTES)
#define BBUF(b) ((b) * 2 * TILE_BYTES + TILE_BYTES)
#define SMEM_DYN (NSTAGE * 2 * TILE_BYTES)   // 110592 bytes

// Scratch (device globals -- no allocation allowed; zero-initialized)
__device__ __half g_normh[BATCH * DIM];  // fp16 normalized features (4 MB)
__device__ int    g_cls[BATCH];
__device__ float  g_pos[BATCH];
__device__ float  g_all[BATCH];
__device__ unsigned g_done;              // CTA completion counter (self-resetting)

// ---------------------------------------------------------------------------
__device__ __forceinline__ uint32_t smem_u32(const void* p) {
    uint32_t a;
    asm("{ .reg .u64 t; cvta.to.shared.u64 t, %1; cvt.u32.u64 %0, t; }"
        : "=r"(a) : "l"(p));
    return a;
}

#define LDSM_X4(d, addr) \
    asm volatile("ldmatrix.sync.aligned.m8n8.x4.shared.b16 {%0,%1,%2,%3}, [%4];" \
                 : "=r"((d)[0]), "=r"((d)[1]), "=r"((d)[2]), "=r"((d)[3]) \
                 : "r"(addr))

// fp16 accumulate m16n8k16 -- measured best legacy tensor rate on sm_103
__device__ __forceinline__ void mma_f16h(uint32_t* c, const uint32_t* a,
                                         uint32_t b0, uint32_t b1) {
    asm volatile(
        "mma.sync.aligned.m16n8k16.row.col.f16.f16.f16.f16 "
        "{%0,%1}, {%2,%3,%4,%5}, {%6,%7}, {%0,%1};"
        : "+r"(c[0]), "+r"(c[1])
        : "r"(a[0]), "r"(a[1]), "r"(a[2]), "r"(a[3]), "r"(b0), "r"(b1));
}

__device__ __forceinline__ float fast_exp2(float x) {
    float r;
    asm("ex2.approx.ftz.f32 %0, %1;" : "=f"(r) : "f"(x));
    return r;
}

__device__ __forceinline__ uint32_t pack_h2(float a, float b) {
    uint32_t r;
    asm("{ .reg .b16 l, h;\n\t"
        "cvt.rn.f16.f32 l, %1;\n\t"
        "cvt.rn.f16.f32 h, %2;\n\t"
        "mov.b32 %0, {l, h}; }" : "=r"(r) : "f"(a), "f"(b));
    return r;
}

// ---------------------------------------------------------------------------
// Kernel 1: L2-normalize -> fp16, class id, zero accumulators. Warp per row.
// (Proven 6.2us configuration.)
// ---------------------------------------------------------------------------
__global__ void __launch_bounds__(256)
normalize_kernel(const float* __restrict__ feats,
                 const float* __restrict__ labels) {
    const int wid = threadIdx.x >> 5;
    const int lane = threadIdx.x & 31;
    const int row = blockIdx.x * 8 + wid;

    float4 v[4];
    float ss = 0.0f;
#pragma unroll
    for (int k = 0; k < 4; k++) {
        v[k] = ((const float4*)(feats + row * DIM))[k * 32 + lane];
        ss += v[k].x * v[k].x + v[k].y * v[k].y + v[k].z * v[k].z + v[k].w * v[k].w;
    }
#pragma unroll
    for (int o = 16; o > 0; o >>= 1) ss += __shfl_xor_sync(0xffffffffu, ss, o);
    float inv = 1.0f / sqrtf(ss);

#pragma unroll
    for (int k = 0; k < 4; k++) {
        uint2 u;
        u.x = pack_h2(v[k].x * inv, v[k].y * inv);
        u.y = pack_h2(v[k].z * inv, v[k].w * inv);
        ((uint2*)(g_normh + row * DIM))[k * 32 + lane] = u;
    }

    if (lane < NCLS) {
        if (labels[row * NCLS + lane] > 0.5f) g_cls[row] = lane;
    }
    if (lane == 0) { g_pos[row] = 0.0f; g_all[row] = 0.0f; }
}

// ---------------------------------------------------------------------------
// Kernel 2: fp16-accumulate m16n8k16 symmetric Gram tile, 3-stage cp.async
// pipeline, K chunks of 64; 512 threads = 16 warps (4x4), 32x32 warp tiles.
// Fused finalize: last CTA (release-ordered counter) reduces the loss.
// ---------------------------------------------------------------------------
__global__ void __launch_bounds__(512, 2)
contrastive_mma_kernel(float* __restrict__ out) {
    extern __shared__ char smem[];
    __shared__ int clsA_s[128];
    __shared__ int clsB_s[128];
    __shared__ unsigned s_last;
    const uint32_t sb = smem_u32(smem);

    const int tid = threadIdx.x;
    const int lane = tid & 31;
    const int wid = tid >> 5;
    const int wr = wid >> 2;        // 0..3 warp row (32 rows each)
    const int wc = wid & 3;         // 0..3 warp col (32 cols each)
    const int g = lane >> 2;        // 0..7
    const int tig = lane & 3;       // 0..3

    // map linear block index -> upper-triangular (by, bx), bx >= by
    int rem = blockIdx.x;
    int by = 0;
    while (rem >= (NBLK - by)) { rem -= (NBLK - by); by++; }
    const int bx = by + rem;
    const bool isDiag = (bx == by);
    const int rowBase = by * BM;
    const int colBase = bx * BM;

    if (tid < 128) clsA_s[tid] = g_cls[rowBase + tid];
    else if (tid < 256) clsB_s[tid - 128] = g_cls[colBase + (tid - 128)];

    // per-lane ldmatrix offsets (bytes within tile)
    const int mA = lane >> 3;       // matrix index 0..3
    const int rA = lane & 7;
    const uint32_t aOff = (uint32_t)((wr * 32 + (mA & 1) * 8 + rA) * RSTRIDE
                                     + (mA >> 1) * 16);
    const uint32_t bOff = (uint32_t)((wc * 32 + (mA >> 1) * 8 + rA) * RSTRIDE
                                     + (mA & 1) * 16);

    // fp16 accumulators: [mi][ni][h] -> b32 holding cols (tig*2, tig*2+1)
    uint32_t hacc[2][4][2];
#pragma unroll
    for (int mi = 0; mi < 2; mi++)
#pragma unroll
        for (int ni = 0; ni < 4; ni++) {
            hacc[mi][ni][0] = 0u;
            hacc[mi][ni][1] = 0u;
        }

    auto load_chunk = [&](int c) {
        const int buf = c % NSTAGE;
        const int k0 = c * KCHUNK;
#pragma unroll
        for (int it = 0; it < 4; it++) {
            int flat = it * 512 + tid;      // 0..2047 16B segments
            int tile = flat >> 10;          // 0 = A, 1 = B
            if (tile == 1 && isDiag) continue;   // diag: B aliases A
            int r = (flat >> 3) & 127;
            int seg = flat & 7;
            const __half* src = g_normh
                + (size_t)((tile ? colBase : rowBase) + r) * DIM + k0 + seg * 8;
            uint32_t dst = sb + (tile ? BBUF(buf) : ABUF(buf))
                         + r * RSTRIDE + seg * 16;
            asm volatile("cp.async.cg.shared.global [%0], [%1], 16;"
                         :: "r"(dst), "l"(src) : "memory");
        }
        asm volatile("cp.async.commit_group;" ::: "memory");
    };

    auto compute_chunk = [&](int buf) {
        const uint32_t aBase = sb + ABUF(buf) + aOff;
        const uint32_t bBase = (isDiag ? sb + ABUF(buf) : sb + BBUF(buf)) + bOff;
#pragma unroll
        for (int ks = 0; ks < 4; ks++) {       // four k16 steps per 64-chunk
            uint32_t a[2][4], b[2][4];
#pragma unroll
            for (int mi = 0; mi < 2; mi++)
                LDSM_X4(a[mi], aBase + mi * (16 * RSTRIDE) + ks * 32);
#pragma unroll
            for (int p = 0; p < 2; p++)        // p covers cols wc*32 + p*16
                LDSM_X4(b[p], bBase + p * (16 * RSTRIDE) + ks * 32);
#pragma unroll
            for (int mi = 0; mi < 2; mi++)
#pragma unroll
                for (int ni = 0; ni < 4; ni++)
                    mma_f16h(hacc[mi][ni], a[mi],
                             b[ni >> 1][2 * (ni & 1)], b[ni >> 1][2 * (ni & 1) + 1]);
        }
    };

    // ---- 3-stage pipelined mainloop: one __syncthreads per chunk ----
    load_chunk(0);
    load_chunk(1);
    for (int c = 0; c < NCHUNK; c++) {
        if (c < NCHUNK - 1)
            asm volatile("cp.async.wait_group 1;" ::: "memory");
        else
            asm volatile("cp.async.wait_group 0;" ::: "memory");
        __syncthreads();
        if (c + 2 < NCHUNK) load_chunk(c + 2);
        compute_chunk(c % NSTAGE);
    }

    // ---- register-only epilogue (no clip: |sim|<=1 -> |sim/T|<=14.3 < 20) ----
    const float SCL = 1.44269504088896f / 0.07f;   // exp(x/T) = exp2(x*SCL)

    int rcls[2][2], ccls[4][2];
#pragma unroll
    for (int mi = 0; mi < 2; mi++)
#pragma unroll
        for (int h = 0; h < 2; h++)
            rcls[mi][h] = clsA_s[wr * 32 + mi * 16 + h * 8 + g];
#pragma unroll
    for (int ni = 0; ni < 4; ni++)
#pragma unroll
        for (int q = 0; q < 2; q++)
            ccls[ni][q] = clsB_s[wc * 32 + ni * 8 + tig * 2 + q];

    float rAll[2][2], rPos[2][2], cAll[4][2], cPos[4][2];
#pragma unroll
    for (int i = 0; i < 2; i++)
#pragma unroll
        for (int h = 0; h < 2; h++) { rAll[i][h] = 0.0f; rPos[i][h] = 0.0f; }
#pragma unroll
    for (int i = 0; i < 4; i++)
#pragma unroll
        for (int q = 0; q < 2; q++) { cAll[i][q] = 0.0f; cPos[i][q] = 0.0f; }

#pragma unroll
    for (int mi = 0; mi < 2; mi++)
#pragma unroll
        for (int ni = 0; ni < 4; ni++)
#pragma unroll
            for (int h = 0; h < 2; h++) {
                float2 vv = __half22float2(
                    *reinterpret_cast<__half2*>(&hacc[mi][ni][h]));
#pragma unroll
                for (int q = 0; q < 2; q++) {
                    float e = fast_exp2((q ? vv.y : vv.x) * SCL);
                    if (isDiag) {
                        int rl = wr * 32 + mi * 16 + h * 8 + g;
                        int cl = wc * 32 + ni * 8 + tig * 2 + q;
                        if (rl == cl) e = 0.0f;
                    }
                    rAll[mi][h] += e;
                    cAll[ni][q] += e;
                    if (rcls[mi][h] == ccls[ni][q]) {
                        rPos[mi][h] += e;
                        cPos[ni][q] += e;
                    }
                }
            }

    // row sums: reduce over tig (lane bits 0,1)
#pragma unroll
    for (int mi = 0; mi < 2; mi++)
#pragma unroll
        for (int h = 0; h < 2; h++) {
#pragma unroll
            for (int o = 1; o < 4; o <<= 1) {
                rAll[mi][h] += __shfl_xor_sync(0xffffffffu, rAll[mi][h], o);
                rPos[mi][h] += __shfl_xor_sync(0xffffffffu, rPos[mi][h], o);
            }
        }
    if (tig == 0) {
#pragma unroll
        for (int mi = 0; mi < 2; mi++)
#pragma unroll
            for (int h = 0; h < 2; h++) {
                int gr = rowBase + wr * 32 + mi * 16 + h * 8 + g;
                atomicAdd(&g_all[gr], rAll[mi][h]);
                atomicAdd(&g_pos[gr], rPos[mi][h]);
            }
    }

    // symmetric column sums (off-diagonal only): reduce over g (lane bits 2..4)
    if (!isDiag) {
#pragma unroll
        for (int ni = 0; ni < 4; ni++)
#pragma unroll
            for (int q = 0; q < 2; q++) {
#pragma unroll
                for (int o = 4; o < 32; o <<= 1) {
                    cAll[ni][q] += __shfl_xor_sync(0xffffffffu, cAll[ni][q], o);
                    cPos[ni][q] += __shfl_xor_sync(0xffffffffu, cPos[ni][q], o);
                }
            }
        if (g == 0) {
#pragma unroll
            for (int ni = 0; ni < 4; ni++)
#pragma unroll
                for (int q = 0; q < 2; q++) {
                    int gc = colBase + wc * 32 + ni * 8 + tig * 2 + q;
                    atomicAdd(&g_all[gc], cAll[ni][q]);
                    atomicAdd(&g_pos[gc], cPos[ni][q]);
                }
        }
    }

    // ---- fused finalize (validated in R14): release-ordered counter, last
    // CTA reduces from L2. Epilogue writes are all L2 atomics, so the release
    // on the counter orders them without any L1 flush.
    if (tid == 0) {
        unsigned old;
        asm volatile("atom.acq_rel.gpu.global.add.u32 %0, [%1], 1;"
                     : "=r"(old) : "l"(&g_done) : "memory");
        s_last = old;
    }
    __syncthreads();
    if (s_last == NTRI - 1) {
        __shared__ int cnt[NCLS];
        __shared__ float s_tot[16];
        __shared__ float s_cnt[16];
        if (tid < NCLS) cnt[tid] = 0;
        __syncthreads();
        for (int r = tid; r < BATCH; r += 512)
            atomicAdd(&cnt[__ldcg(&g_cls[r])], 1);
        __syncthreads();

        float total = 0.0f, nval = 0.0f;
        for (int r = tid; r < BATCH; r += 512) {
            int c = __ldcg(&g_cls[r]);
            if (cnt[c] >= 2) {
                float pos = __ldcg(&g_pos[r]);
                float all = __ldcg(&g_all[r]);
                total += -logf(pos / (all + 1e-8f) + 1e-8f);
                nval += 1.0f;
            }
        }
#pragma unroll
        for (int o = 16; o > 0; o >>= 1) {
            total += __shfl_xor_sync(0xffffffffu, total, o);
            nval  += __shfl_xor_sync(0xffffffffu, nval, o);
        }
        if (lane == 0) { s_tot[wid] = total; s_cnt[wid] = nval; }
        __syncthreads();
        if (tid == 0) {
            float tt = 0.0f, nn = 0.0f;
#pragma unroll
            for (int w = 0; w < 16; w++) { tt += s_tot[w]; nn += s_cnt[w]; }
            out[0] = (nn > 0.0f) ? tt / nn : 0.0f;
            g_done = 0;   // reset for next graph replay
        }
    }
}

// ---------------------------------------------------------------------------
extern "C" void kernel_launch(void* const* d_in, const int* in_sizes, int n_in,
                              void* d_out, int out_size) {
    const float* features = (const float*)d_in[0];  // [4096, 512] f32
    const float* labels   = (const float*)d_in[1];  // [4096, 10]  f32
    float* out = (float*)d_out;

    cudaFuncSetAttribute(contrastive_mma_kernel,
                         cudaFuncAttributeMaxDynamicSharedMemorySize, SMEM_DYN);

    normalize_kernel<<<BATCH / 8, 256>>>(features, labels);
    contrastive_mma_kernel<<<NTRI, 512, SMEM_DYN>>>(out);
}

// round 16
// speedup vs baseline: 1.2139x; 1.1050x over previous
#include <cuda_runtime.h>
#include <cuda_fp16.h>
#include <math.h>
#include <stdint.h>

#define BATCH 4096
#define DIM   512
#define NCLS  10

#define BM 128
#define NBLK (BATCH / BM)            // 32
#define NTRI (NBLK * (NBLK + 1) / 2) // 528 upper-triangular tiles

#define NCHUNK 8                     // K chunks of 64 halves
#define KCHUNK 64
#define NSTAGE 3

#define RSTRIDE 144                          // bytes per smem row (64 fp16 + 16B pad)
#define TILE_BYTES (128 * RSTRIDE)           // 18432
#define ABUF(b) ((b) * 2 * TILE_BYTES)
#define BBUF(b) ((b) * 2 * TILE_BYTES + TILE_BYTES)
#define SMEM_DYN (NSTAGE * 2 * TILE_BYTES)   // 110592 bytes

// Scratch (device globals -- no allocation allowed)
__device__ __half g_normh[BATCH * DIM];  // fp16 normalized features (4 MB)
__device__ int    g_cls[BATCH];
__device__ float  g_pos[BATCH];
__device__ float  g_all[BATCH];

// ---------------------------------------------------------------------------
__device__ __forceinline__ uint32_t smem_u32(const void* p) {
    uint32_t a;
    asm("{ .reg .u64 t; cvta.to.shared.u64 t, %1; cvt.u32.u64 %0, t; }"
        : "=r"(a) : "l"(p));
    return a;
}

#define LDSM_X4(d, addr) \
    asm volatile("ldmatrix.sync.aligned.m8n8.x4.shared.b16 {%0,%1,%2,%3}, [%4];" \
                 : "=r"((d)[0]), "=r"((d)[1]), "=r"((d)[2]), "=r"((d)[3]) \
                 : "r"(addr))

// fp16 accumulate m16n8k16 -- measured best legacy tensor rate on sm_103
__device__ __forceinline__ void mma_f16h(uint32_t* c, const uint32_t* a,
                                         uint32_t b0, uint32_t b1) {
    asm volatile(
        "mma.sync.aligned.m16n8k16.row.col.f16.f16.f16.f16 "
        "{%0,%1}, {%2,%3,%4,%5}, {%6,%7}, {%0,%1};"
        : "+r"(c[0]), "+r"(c[1])
        : "r"(a[0]), "r"(a[1]), "r"(a[2]), "r"(a[3]), "r"(b0), "r"(b1));
}

__device__ __forceinline__ float fast_exp2(float x) {
    float r;
    asm("ex2.approx.ftz.f32 %0, %1;" : "=f"(r) : "f"(x));
    return r;
}

__device__ __forceinline__ uint32_t pack_h2(float a, float b) {
    uint32_t r;
    asm("{ .reg .b16 l, h;\n\t"
        "cvt.rn.f16.f32 l, %1;\n\t"
        "cvt.rn.f16.f32 h, %2;\n\t"
        "mov.b32 %0, {l, h}; }" : "=r"(r) : "f"(a), "f"(b));
    return r;
}

// ---------------------------------------------------------------------------
// Kernel 1: L2-normalize -> fp16, class id, zero accumulators. Warp per row.
// Triggers the dependent MMA grid launch as soon as its stores are issued.
// ---------------------------------------------------------------------------
__global__ void __launch_bounds__(256)
normalize_kernel(const float* __restrict__ feats,
                 const float* __restrict__ labels) {
    const int wid = threadIdx.x >> 5;
    const int lane = threadIdx.x & 31;
    const int row = blockIdx.x * 8 + wid;

    float4 v[4];
    float ss = 0.0f;
#pragma unroll
    for (int k = 0; k < 4; k++) {
        v[k] = ((const float4*)(feats + row * DIM))[k * 32 + lane];
        ss += v[k].x * v[k].x + v[k].y * v[k].y + v[k].z * v[k].z + v[k].w * v[k].w;
    }
#pragma unroll
    for (int o = 16; o > 0; o >>= 1) ss += __shfl_xor_sync(0xffffffffu, ss, o);
    float inv = 1.0f / sqrtf(ss);

#pragma unroll
    for (int k = 0; k < 4; k++) {
        uint2 u;
        u.x = pack_h2(v[k].x * inv, v[k].y * inv);
        u.y = pack_h2(v[k].z * inv, v[k].w * inv);
        ((uint2*)(g_normh + row * DIM))[k * 32 + lane] = u;
    }

    if (lane < NCLS) {
        if (labels[row * NCLS + lane] > 0.5f) g_cls[row] = lane;
    }
    if (lane == 0) { g_pos[row] = 0.0f; g_all[row] = 0.0f; }

#if __CUDA_ARCH__ >= 900
    cudaTriggerProgrammaticLaunchCompletion();
#endif
}

// ---------------------------------------------------------------------------
// Kernel 2: fp16-accumulate m16n8k16 symmetric Gram tile, 3-stage cp.async
// pipeline, K chunks of 64; 512 threads = 16 warps (4x4), 32x32 warp tiles.
// PDL: prologue (index math) runs before gridDepSync; data reads after.
// ---------------------------------------------------------------------------
__global__ void __launch_bounds__(512, 2)
contrastive_mma_kernel() {
    extern __shared__ char smem[];
    __shared__ int clsA_s[128];
    __shared__ int clsB_s[128];
    const uint32_t sb = smem_u32(smem);

    const int tid = threadIdx.x;
    const int lane = tid & 31;
    const int wid = tid >> 5;
    const int wr = wid >> 2;        // 0..3 warp row (32 rows each)
    const int wc = wid & 3;         // 0..3 warp col (32 cols each)
    const int g = lane >> 2;        // 0..7
    const int tig = lane & 3;       // 0..3

    // map linear block index -> upper-triangular (by, bx), bx >= by
    int rem = blockIdx.x;
    int by = 0;
    while (rem >= (NBLK - by)) { rem -= (NBLK - by); by++; }
    const int bx = by + rem;
    const bool isDiag = (bx == by);
    const int rowBase = by * BM;
    const int colBase = bx * BM;

    // per-lane ldmatrix offsets (bytes within tile)
    const int mA = lane >> 3;       // matrix index 0..3
    const int rA = lane & 7;
    const uint32_t aOff = (uint32_t)((wr * 32 + (mA & 1) * 8 + rA) * RSTRIDE
                                     + (mA >> 1) * 16);
    const uint32_t bOff = (uint32_t)((wc * 32 + (mA >> 1) * 8 + rA) * RSTRIDE
                                     + (mA & 1) * 16);

    // fp16 accumulators: [mi][ni][h] -> b32 holding cols (tig*2, tig*2+1)
    uint32_t hacc[2][4][2];
#pragma unroll
    for (int mi = 0; mi < 2; mi++)
#pragma unroll
        for (int ni = 0; ni < 4; ni++) {
            hacc[mi][ni][0] = 0u;
            hacc[mi][ni][1] = 0u;
        }

#if __CUDA_ARCH__ >= 900
    cudaGridDependencySynchronize();   // wait for normalize's memory flush
#endif

    if (tid < 128) clsA_s[tid] = g_cls[rowBase + tid];
    else if (tid < 256) clsB_s[tid - 128] = g_cls[colBase + (tid - 128)];

    auto load_chunk = [&](int c) {
        const int buf = c % NSTAGE;
        const int k0 = c * KCHUNK;
#pragma unroll
        for (int it = 0; it < 4; it++) {
            int flat = it * 512 + tid;      // 0..2047 16B segments
            int tile = flat >> 10;          // 0 = A, 1 = B
            if (tile == 1 && isDiag) continue;   // diag: B aliases A
            int r = (flat >> 3) & 127;
            int seg = flat & 7;
            const __half* src = g_normh
                + (size_t)((tile ? colBase : rowBase) + r) * DIM + k0 + seg * 8;
            uint32_t dst = sb + (tile ? BBUF(buf) : ABUF(buf))
                         + r * RSTRIDE + seg * 16;
            asm volatile("cp.async.cg.shared.global [%0], [%1], 16;"
                         :: "r"(dst), "l"(src) : "memory");
        }
        asm volatile("cp.async.commit_group;" ::: "memory");
    };

    auto compute_chunk = [&](int buf) {
        const uint32_t aBase = sb + ABUF(buf) + aOff;
        const uint32_t bBase = (isDiag ? sb + ABUF(buf) : sb + BBUF(buf)) + bOff;
#pragma unroll
        for (int ks = 0; ks < 4; ks++) {       // four k16 steps per 64-chunk
            uint32_t a[2][4], b[2][4];
#pragma unroll
            for (int mi = 0; mi < 2; mi++)
                LDSM_X4(a[mi], aBase + mi * (16 * RSTRIDE) + ks * 32);
#pragma unroll
            for (int p = 0; p < 2; p++)        // p covers cols wc*32 + p*16
                LDSM_X4(b[p], bBase + p * (16 * RSTRIDE) + ks * 32);
#pragma unroll
            for (int mi = 0; mi < 2; mi++)
#pragma unroll
                for (int ni = 0; ni < 4; ni++)
                    mma_f16h(hacc[mi][ni], a[mi],
                             b[ni >> 1][2 * (ni & 1)], b[ni >> 1][2 * (ni & 1) + 1]);
        }
    };

    // ---- 3-stage pipelined mainloop: one __syncthreads per chunk ----
    load_chunk(0);
    load_chunk(1);
    for (int c = 0; c < NCHUNK; c++) {
        if (c < NCHUNK - 1)
            asm volatile("cp.async.wait_group 1;" ::: "memory");
        else
            asm volatile("cp.async.wait_group 0;" ::: "memory");
        __syncthreads();
        if (c + 2 < NCHUNK) load_chunk(c + 2);
        compute_chunk(c % NSTAGE);
    }

    // ---- register-only epilogue (no clip: |sim|<=1 -> |sim/T|<=14.3 < 20) ----
    const float SCL = 1.44269504088896f / 0.07f;   // exp(x/T) = exp2(x*SCL)

    int rcls[2][2], ccls[4][2];
#pragma unroll
    for (int mi = 0; mi < 2; mi++)
#pragma unroll
        for (int h = 0; h < 2; h++)
            rcls[mi][h] = clsA_s[wr * 32 + mi * 16 + h * 8 + g];
#pragma unroll
    for (int ni = 0; ni < 4; ni++)
#pragma unroll
        for (int q = 0; q < 2; q++)
            ccls[ni][q] = clsB_s[wc * 32 + ni * 8 + tig * 2 + q];

    float rAll[2][2], rPos[2][2], cAll[4][2], cPos[4][2];
#pragma unroll
    for (int i = 0; i < 2; i++)
#pragma unroll
        for (int h = 0; h < 2; h++) { rAll[i][h] = 0.0f; rPos[i][h] = 0.0f; }
#pragma unroll
    for (int i = 0; i < 4; i++)
#pragma unroll
        for (int q = 0; q < 2; q++) { cAll[i][q] = 0.0f; cPos[i][q] = 0.0f; }

#pragma unroll
    for (int mi = 0; mi < 2; mi++)
#pragma unroll
        for (int ni = 0; ni < 4; ni++)
#pragma unroll
            for (int h = 0; h < 2; h++) {
                float2 vv = __half22float2(
                    *reinterpret_cast<__half2*>(&hacc[mi][ni][h]));
#pragma unroll
                for (int q = 0; q < 2; q++) {
                    float e = fast_exp2((q ? vv.y : vv.x) * SCL);
                    if (isDiag) {
                        int rl = wr * 32 + mi * 16 + h * 8 + g;
                        int cl = wc * 32 + ni * 8 + tig * 2 + q;
                        if (rl == cl) e = 0.0f;
                    }
                    rAll[mi][h] += e;
                    cAll[ni][q] += e;
                    if (rcls[mi][h] == ccls[ni][q]) {
                        rPos[mi][h] += e;
                        cPos[ni][q] += e;
                    }
                }
            }

    // row sums: reduce over tig (lane bits 0,1)
#pragma unroll
    for (int mi = 0; mi < 2; mi++)
#pragma unroll
        for (int h = 0; h < 2; h++) {
#pragma unroll
            for (int o = 1; o < 4; o <<= 1) {
                rAll[mi][h] += __shfl_xor_sync(0xffffffffu, rAll[mi][h], o);
                rPos[mi][h] += __shfl_xor_sync(0xffffffffu, rPos[mi][h], o);
            }
        }
    if (tig == 0) {
#pragma unroll
        for (int mi = 0; mi < 2; mi++)
#pragma unroll
            for (int h = 0; h < 2; h++) {
                int gr = rowBase + wr * 32 + mi * 16 + h * 8 + g;
                atomicAdd(&g_all[gr], rAll[mi][h]);
                atomicAdd(&g_pos[gr], rPos[mi][h]);
            }
    }

    // symmetric column sums (off-diagonal only): reduce over g (lane bits 2..4)
    if (!isDiag) {
#pragma unroll
        for (int ni = 0; ni < 4; ni++)
#pragma unroll
            for (int q = 0; q < 2; q++) {
#pragma unroll
                for (int o = 4; o < 32; o <<= 1) {
                    cAll[ni][q] += __shfl_xor_sync(0xffffffffu, cAll[ni][q], o);
                    cPos[ni][q] += __shfl_xor_sync(0xffffffffu, cPos[ni][q], o);
                }
            }
        if (g == 0) {
#pragma unroll
            for (int ni = 0; ni < 4; ni++)
#pragma unroll
                for (int q = 0; q < 2; q++) {
                    int gc = colBase + wc * 32 + ni * 8 + tig * 2 + q;
                    atomicAdd(&g_all[gc], cAll[ni][q]);
                    atomicAdd(&g_pos[gc], cPos[ni][q]);
                }
        }
    }

#if __CUDA_ARCH__ >= 900
    cudaTriggerProgrammaticLaunchCompletion();
#endif
}

// ---------------------------------------------------------------------------
// Kernel 3: per-row loss + validity + mean  (single block, 1024 threads).
// PDL: smem init before gridDepSync.
// ---------------------------------------------------------------------------
__global__ void finalize_kernel(float* __restrict__ out) {
    __shared__ int cnt[NCLS];
    __shared__ float s_tot[32];
    __shared__ float s_cnt[32];
    int t = threadIdx.x;  // 1024

    if (t < NCLS) cnt[t] = 0;
    __syncthreads();

#if __CUDA_ARCH__ >= 900
    cudaGridDependencySynchronize();   // wait for MMA grid's memory flush
#endif

    for (int r = t; r < BATCH; r += 1024) atomicAdd(&cnt[g_cls[r]], 1);
    __syncthreads();

    float total = 0.0f, nval = 0.0f;
    for (int r = t; r < BATCH; r += 1024) {
        int c = g_cls[r];
        if (cnt[c] >= 2) {
            float pos = g_pos[r];
            float all = g_all[r];
            total += -logf(pos / (all + 1e-8f) + 1e-8f);
            nval += 1.0f;
        }
    }
#pragma unroll
    for (int o = 16; o > 0; o >>= 1) {
        total += __shfl_xor_sync(0xffffffffu, total, o);
        nval  += __shfl_xor_sync(0xffffffffu, nval, o);
    }
    if ((t & 31) == 0) { s_tot[t >> 5] = total; s_cnt[t >> 5] = nval; }
    __syncthreads();
    if (t == 0) {
        float tt = 0.0f, nn = 0.0f;
#pragma unroll
        for (int w = 0; w < 32; w++) { tt += s_tot[w]; nn += s_cnt[w]; }
        out[0] = (nn > 0.0f) ? tt / nn : 0.0f;
    }
}

// ---------------------------------------------------------------------------
extern "C" void kernel_launch(void* const* d_in, const int* in_sizes, int n_in,
                              void* d_out, int out_size) {
    const float* features = (const float*)d_in[0];  // [4096, 512] f32
    const float* labels   = (const float*)d_in[1];  // [4096, 10]  f32
    float* out = (float*)d_out;

    cudaFuncSetAttribute(contrastive_mma_kernel,
                         cudaFuncAttributeMaxDynamicSharedMemorySize, SMEM_DYN);

    normalize_kernel<<<BATCH / 8, 256>>>(features, labels);

    // MMA kernel with programmatic dependent launch (overlaps launch with
    // normalize tail; gridDepSync inside guards the data dependency).
    {
        cudaLaunchAttribute attr[1];
        attr[0].id = cudaLaunchAttributeProgrammaticStreamSerialization;
        attr[0].val.programmaticStreamSerializationAllowed = 1;
        cudaLaunchConfig_t cfg = {};
        cfg.gridDim = dim3(NTRI);
        cfg.blockDim = dim3(512);
        cfg.dynamicSmemBytes = SMEM_DYN;
        cfg.stream = 0;
        cfg.attrs = attr;
        cfg.numAttrs = 1;
        cudaLaunchKernelEx(&cfg, contrastive_mma_kernel);
    }

    // finalize with PDL off the MMA grid
    {
        cudaLaunchAttribute attr[1];
        attr[0].id = cudaLaunchAttributeProgrammaticStreamSerialization;
        attr[0].val.programmaticStreamSerializationAllowed = 1;
        cudaLaunchConfig_t cfg = {};
        cfg.gridDim = dim3(1);
        cfg.blockDim = dim3(1024);
        cfg.dynamicSmemBytes = 0;
        cfg.stream = 0;
        cfg.attrs = attr;
        cfg.numAttrs = 1;
        cudaLaunchKernelEx(&cfg, finalize_kernel, out);
    }
}